// round 6
// baseline (speedup 1.0000x reference)
#include <cuda_runtime.h>

// ============================================================================
// CSNN (T=8, B=32) as ONE persistent megakernel: 10 stages separated by
// software grid barriers (128 co-resident blocks). Spiking sparsity via
// per-channel validity flags; flat bias-IF paths when a block's input is all
// zero; full tiled conv / gemm fallbacks keep data-dependent correctness.
// Layout: [T][B][C][H][W] row-major, n = t*32 + b.
// ============================================================================

#define TSTEPS 8
#define BATCH  32
#define NBLK   128
#define NTHR   256

typedef unsigned char u8;
typedef unsigned int  u32;

// ---------------- static scratch ----------------
__device__ u8    g_s1 [8*32*128*26*26];
__device__ u8    g_s2 [8*32*128*13*13];
__device__ u8    g_s3 [8*32*192*13*13];
__device__ u8    g_s4 [8*32*128*13*13];
__device__ u8    g_s5 [8*32*128*6*6];
__device__ float g_zf1[8*32*2048];
__device__ u8    g_sf1[8*32*2048];
__device__ float g_zf2[8*32*512];
__device__ u8    g_sf2[8*32*512];

// per-channel validity flags (u8 per (n,c)), rewritten unconditionally each run
__device__ u8 g_f1[256*128];
__device__ u8 g_f2[256*128];
__device__ u8 g_f3[256*192];
__device__ u8 g_f4[256*128];

// global any-flags: gany5 @0 (8), ganyf1 @8 (128), ganyf2 @136 (32)
#define NGZ 168
__device__ u32 g_gz[NGZ];

// grid barrier state (generation counting; persists safely across replays)
__device__ u32 g_barcnt;
__device__ u32 g_bargen;

__device__ __forceinline__ void gsync()
{
    __syncthreads();
    if (threadIdx.x == 0) {
        u32 gen = *(volatile u32*)&g_bargen;
        __threadfence();
        if (atomicAdd(&g_barcnt, 1u) == NBLK - 1) {
            g_barcnt = 0;
            __threadfence();
            atomicAdd(&g_bargen, 1u);
        } else {
            while (*(volatile u32*)&g_bargen == gen) { }
        }
    }
    __syncthreads();
}

#define SMEM_BYTES 17920

// ---------------------------------------------------------------------------
// Stage 0 item: conv1 (1ch, 5x5, s1, p1) for one (image, 16-oc group), conv
// computed ONCE (time-invariant input), IF scan over T. Gated spike stores.
// ---------------------------------------------------------------------------
__device__ void conv1_item(char* smraw, int n, int oc0,
    const float* __restrict__ x, const float* __restrict__ w,
    const float* __restrict__ b, u8* __restrict__ s1, u8* __restrict__ f1,
    float vth)
{
    float* sx    = (float*)smraw;            // 900
    float* sw    = sx + 900;                 // 16*28
    u32*   sflag = (u32*)(sw + 16*28);       // 16 (per-oc 8-bit t masks)
    u8*    smask = (u8*)(sflag + 16);        // 676*16
    const int tid = threadIdx.x;

    __syncthreads();                         // smem reuse fence
    #pragma unroll 1
    for (int i = tid; i < 900; i += NTHR) {
        int r = i / 30, c = i - 30*r;
        float v = 0.f;
        if (r >= 1 && r < 29 && c >= 1 && c < 29)
            v = x[n*784 + (r-1)*28 + (c-1)];
        sx[i] = v;
    }
    #pragma unroll 1
    for (int i = tid; i < 16*25; i += NTHR) {
        int oc = i / 25, k = i - oc*25;
        sw[oc*28 + k] = w[(oc0 + oc)*25 + k];
    }
    if (tid < 16) sflag[tid] = 0u;
    __syncthreads();

    float bv[16];
    #pragma unroll
    for (int oc = 0; oc < 16; oc++) bv[oc] = __ldg(&b[oc0 + oc]);

    #pragma unroll 1
    for (int pos = tid; pos < 676; pos += NTHR) {
        int oy = pos / 26, ox = pos - 26*oy;
        float xv[25];
        #pragma unroll
        for (int ky = 0; ky < 5; ky++)
            #pragma unroll
            for (int kx = 0; kx < 5; kx++)
                xv[ky*5 + kx] = sx[(oy+ky)*30 + ox+kx];
        #pragma unroll
        for (int oc = 0; oc < 16; oc++) {
            float a = bv[oc];
            #pragma unroll
            for (int k = 0; k < 25; k++)
                a = fmaf(xv[k], sw[oc*28 + k], a);
            float v = 0.f; u32 bits = 0;
            #pragma unroll
            for (int t = 0; t < TSTEPS; t++) {
                v += a;
                float sp = (v >= vth) ? 1.f : 0.f;
                v -= v * sp;
                if (sp != 0.f) bits |= 1u << t;
            }
            smask[pos*16 + oc] = (u8)bits;
            if (bits) atomicOr(&sflag[oc], bits);
        }
    }
    __syncthreads();

    if (tid < 128) {
        int t = tid >> 4, oc = tid & 15;
        f1[(t*BATCH + n)*128 + oc0 + oc] = (u8)((sflag[oc] >> t) & 1u);
    }
    #pragma unroll 1
    for (int oc = 0; oc < 16; oc++) {
        u32 fb = sflag[oc];
        if (!fb) continue;
        for (int t = 0; t < TSTEPS; t++)
            if ((fb >> t) & 1u)
                for (int pos = tid; pos < 676; pos += NTHR)
                    s1[((size_t)(t*BATCH + n)*128 + oc0 + oc)*676 + pos] =
                        (u8)((smask[pos*16 + oc] >> t) & 1u);
    }
}

// ---------------------------------------------------------------------------
// Conv+IF item for layers 2..5 (one 16-oc tile, one image, all timesteps).
// GATED: flag-gated stores + per-channel flag writes. !GATED (L5):
// unconditional stores + global gany per 16-oc group.
// ---------------------------------------------------------------------------
template <int CIN, int COUT, int IH, int IW, int OH, int OW,
          int KH, int KW, int S, int PAD, int CC, bool GATED>
__device__ void conv_item(char* smraw, int oc0, int b0,
    const u8* __restrict__ in, const float* __restrict__ wgt,
    const float* __restrict__ bias, u8* __restrict__ sout,
    const u8* __restrict__ fin, u8* __restrict__ fout,
    u32* __restrict__ gany, float vth)
{
    constexpr int TC    = 16;
    constexpr int P     = OH * OW;
    constexpr int PIH   = (OH - 1) * S + KH;
    constexpr int PIW   = (OW - 1) * S + KW;
    constexpr int KK    = KH * KW;
    constexpr int KWPAD = (KK + 3) & ~3;
    constexpr int FW    = TSTEPS * CIN / 4;

    float* s_in  = (float*)smraw;                       // CC*PIH*PIW
    float* s_w   = s_in + CC*PIH*PIW;                   // CC*TC*KWPAD
    u32*   s_finw = (u32*)(s_w + CC*TC*KWPAD);          // FW
    const u8* s_finb = (const u8*)s_finw;
    const int tid = threadIdx.x;

    __syncthreads();                                    // smem reuse fence
    #pragma unroll 1
    for (int i = tid; i < FW; i += NTHR) {
        int t = i / (CIN/4), off = i - t*(CIN/4);
        s_finw[i] = ((const u32*)fin)[((t*BATCH + b0)*CIN)/4 + off];
    }
    __syncthreads();

    u32 part = 0;
    #pragma unroll 1
    for (int i = tid; i < FW; i += NTHR)
        if (s_finw[i]) part |= 1u << (i / (CIN/4));
    u32 tmask = (u32)__syncthreads_or((int)part);

    float bi[TC];
    #pragma unroll
    for (int i = 0; i < TC; i++) bi[i] = __ldg(&bias[oc0 + i]);

    if (tmask == 0u) {
        // ---------- FLAT PATH: bias-only IF ----------
        u32 spb[TC]; u32 anyb = 0;
        #pragma unroll
        for (int oc = 0; oc < TC; oc++) {
            float v = 0.f; u32 bits = 0;
            #pragma unroll
            for (int t = 0; t < TSTEPS; t++) {
                v += bi[oc];
                float sp = (v >= vth) ? 1.f : 0.f;
                v -= v * sp;
                if (sp != 0.f) bits |= 1u << t;
            }
            spb[oc] = bits; anyb |= bits;
        }
        if (GATED) {
            #pragma unroll 1
            for (int i = tid; i < TSTEPS*TC; i += NTHR) {
                int t = i / TC, oc = i - t*TC;
                fout[(t*BATCH + b0)*COUT + oc0 + oc] = (u8)((spb[oc] >> t) & 1u);
            }
            if (anyb) {
                #pragma unroll 1
                for (int oc = 0; oc < TC; oc++) {
                    if (!spb[oc]) continue;
                    for (int t = 0; t < TSTEPS; t++)
                        if ((spb[oc] >> t) & 1u)
                            for (int p = tid; p < P; p += NTHR)
                                sout[((size_t)(t*BATCH + b0)*COUT + oc0 + oc)*P + p] = 1;
                }
            }
        } else {
            #pragma unroll 1
            for (int i = tid; i < TSTEPS*TC*P; i += NTHR) {
                int t   = i / (TC*P);
                int rem = i - t*(TC*P);
                int oc  = rem / P;
                int p   = rem - oc*P;
                sout[((size_t)(t*BATCH + b0)*COUT + oc0 + oc)*P + p] =
                    (u8)((spb[oc] >> t) & 1u);
            }
            if (anyb && tid == 0) gany[oc0 >> 4] = 1u;
        }
        return;
    }

    // ---------- TILED CONV PATH ----------
    const int pos = tid;
    const bool active = pos < P;
    const int oy = pos / OW;
    const int ox = pos - oy * OW;

    float v[TC];
    #pragma unroll
    for (int i = 0; i < TC; i++) v[i] = 0.f;

    for (int t = 0; t < TSTEPS; t++) {
        float acc[TC];
        #pragma unroll
        for (int i = 0; i < TC; i++) acc[i] = 0.f;

        if ((tmask >> t) & 1u) {
            #pragma unroll 1
            for (int c0 = 0; c0 < CIN; c0 += CC) {
                u32 cz = 0;
                #pragma unroll
                for (int q = 0; q < CC/4; q++)
                    cz |= s_finw[(t*CIN + c0)/4 + q];
                if (!cz) continue;

                #pragma unroll 1
                for (int i = tid; i < CC*PIH*PIW; i += NTHR) {
                    int cc = i / (PIH*PIW);
                    int pp = i - cc*(PIH*PIW);
                    int py = pp / PIW;
                    int px = pp - py*PIW;
                    int iy = py - PAD, ix = px - PAD;
                    float val = 0.f;
                    if (s_finb[t*CIN + c0 + cc] &&
                        iy >= 0 && iy < IH && ix >= 0 && ix < IW)
                        val = (float)in[((size_t)(t*BATCH + b0)*CIN + c0 + cc)*(IH*IW)
                                        + iy*IW + ix];
                    s_in[cc*(PIH*PIW) + pp] = val;
                }
                #pragma unroll 1
                for (int i = tid; i < CC*TC*KK; i += NTHR) {
                    int cc  = i / (TC*KK);
                    int rem = i - cc*(TC*KK);
                    int oc  = rem / KK;
                    int k   = rem - oc*KK;
                    s_w[(cc*TC + oc)*KWPAD + k] = wgt[((oc0 + oc)*CIN + c0 + cc)*KK + k];
                }
                __syncthreads();
                if (active) {
                    #pragma unroll
                    for (int cc = 0; cc < CC; cc++) {
                        float xin[KK];
                        #pragma unroll
                        for (int ky = 0; ky < KH; ky++)
                            #pragma unroll
                            for (int kx = 0; kx < KW; kx++)
                                xin[ky*KW + kx] =
                                    s_in[cc*(PIH*PIW) + (oy*S + ky)*PIW + ox*S + kx];
                        #pragma unroll
                        for (int oc = 0; oc < TC; oc++) {
                            float wv[KWPAD];
                            #pragma unroll
                            for (int q = 0; q < KWPAD/4; q++) {
                                float4 v4 = *reinterpret_cast<const float4*>(
                                    &s_w[(cc*TC + oc)*KWPAD + q*4]);
                                wv[q*4+0] = v4.x; wv[q*4+1] = v4.y;
                                wv[q*4+2] = v4.z; wv[q*4+3] = v4.w;
                            }
                            float a = acc[oc];
                            #pragma unroll
                            for (int k = 0; k < KK; k++)
                                a = fmaf(xin[k], wv[k], a);
                            acc[oc] = a;
                        }
                    }
                }
                __syncthreads();
            }
        }

        u32 myspk = 0;
        if (active) {
            #pragma unroll
            for (int oc = 0; oc < TC; oc++) {
                v[oc] += acc[oc] + bi[oc];
                float sp = (v[oc] >= vth) ? 1.f : 0.f;
                v[oc] -= v[oc] * sp;
                if (sp != 0.f) myspk |= 1u << oc;
            }
        }
        u32 bm = (u32)__syncthreads_or((int)myspk);

        if (GATED) {
            if (tid < TC)
                fout[(t*BATCH + b0)*COUT + oc0 + tid] = (u8)((bm >> tid) & 1u);
            if (active && bm) {
                #pragma unroll
                for (int oc = 0; oc < TC; oc++)
                    if ((bm >> oc) & 1u)
                        sout[((size_t)(t*BATCH + b0)*COUT + oc0 + oc)*P + pos] =
                            (u8)((myspk >> oc) & 1u);
            }
        } else {
            if (active) {
                #pragma unroll
                for (int oc = 0; oc < TC; oc++)
                    sout[((size_t)(t*BATCH + b0)*COUT + oc0 + oc)*P + pos] =
                        (u8)((myspk >> oc) & 1u);
            }
            if (bm && tid == 0) gany[oc0 >> 4] = 1u;
        }
    }
}

// ---------------------------------------------------------------------------
// GEMM stage: C[M,N] = A[M,K](u8) * B[N,K]^T, 64x64x16 tiles per item.
// All-zero input (gany) -> whole stage exits (paired IF stage checks same).
// ---------------------------------------------------------------------------
__device__ void gemm_stage(char* smraw,
    const u8* __restrict__ A, const float* __restrict__ B,
    float* __restrict__ C, int M, int N, int K,
    const u32* __restrict__ gany, int ppc, int ngrp)
{
    float* As    = (float*)smraw;            // 16*64
    float* Bs    = As + 16*64;               // 16*64
    u32*   s_any = (u32*)(Bs + 16*64);       // up to 128
    const int tid = threadIdx.x;

    __syncthreads();
    u32 part = 0;
    #pragma unroll 1
    for (int i = tid; i < ngrp; i += NTHR) {
        u32 g = __ldg(&gany[i]);
        s_any[i] = g;
        part |= g;
    }
    u32 anyall = (u32)__syncthreads_or((int)part);
    if (!anyall) return;

    const int tm = tid >> 4, tn = tid & 15;
    const int r = tid >> 2, q = (tid & 3) << 2;
    const int ntx = N / 64;
    const int ntiles = ntx * (M / 64);

    for (int tile = blockIdx.x; tile < ntiles; tile += NBLK) {
        int n0 = (tile % ntx) * 64;
        int m0 = (tile / ntx) * 64;

        float c[4][4];
        #pragma unroll
        for (int i = 0; i < 4; i++)
            #pragma unroll
            for (int j = 0; j < 4; j++) c[i][j] = 0.f;

        for (int k0 = 0; k0 < K; k0 += 16) {
            int g1 = (k0 / ppc) >> 4;
            int g2 = ((k0 + 15) / ppc) >> 4;
            if (!(s_any[g1] | s_any[g2])) continue;

            uchar4 av = *reinterpret_cast<const uchar4*>(&A[(m0 + r) * K + k0 + q]);
            As[(q+0)*64 + r] = (float)av.x; As[(q+1)*64 + r] = (float)av.y;
            As[(q+2)*64 + r] = (float)av.z; As[(q+3)*64 + r] = (float)av.w;
            int f = av.x | av.y | av.z | av.w;
            if (__syncthreads_or(f)) {
                float4 bv = *reinterpret_cast<const float4*>(&B[(n0 + r) * K + k0 + q]);
                Bs[(q+0)*64 + r] = bv.x; Bs[(q+1)*64 + r] = bv.y;
                Bs[(q+2)*64 + r] = bv.z; Bs[(q+3)*64 + r] = bv.w;
                __syncthreads();
                #pragma unroll
                for (int kk = 0; kk < 16; kk++) {
                    float4 a = *reinterpret_cast<const float4*>(&As[kk*64 + tm*4]);
                    float4 b = *reinterpret_cast<const float4*>(&Bs[kk*64 + tn*4]);
                    c[0][0] = fmaf(a.x, b.x, c[0][0]); c[0][1] = fmaf(a.x, b.y, c[0][1]);
                    c[0][2] = fmaf(a.x, b.z, c[0][2]); c[0][3] = fmaf(a.x, b.w, c[0][3]);
                    c[1][0] = fmaf(a.y, b.x, c[1][0]); c[1][1] = fmaf(a.y, b.y, c[1][1]);
                    c[1][2] = fmaf(a.y, b.z, c[1][2]); c[1][3] = fmaf(a.y, b.w, c[1][3]);
                    c[2][0] = fmaf(a.z, b.x, c[2][0]); c[2][1] = fmaf(a.z, b.y, c[2][1]);
                    c[2][2] = fmaf(a.z, b.z, c[2][2]); c[2][3] = fmaf(a.z, b.w, c[2][3]);
                    c[3][0] = fmaf(a.w, b.x, c[3][0]); c[3][1] = fmaf(a.w, b.y, c[3][1]);
                    c[3][2] = fmaf(a.w, b.z, c[3][2]); c[3][3] = fmaf(a.w, b.w, c[3][3]);
                }
                __syncthreads();
            }
        }
        #pragma unroll
        for (int i = 0; i < 4; i++)
            #pragma unroll
            for (int j = 0; j < 4; j++)
                C[(m0 + tm*4 + i) * N + n0 + tn*4 + j] = c[i][j];
    }
}

// ---------------------------------------------------------------------------
// IF stage for FC layers: exits when the producing gemm's input flags were
// all zero (z untouched; no FC bias => no spikes). Else full scan.
// ---------------------------------------------------------------------------
__device__ void if_stage(const float* __restrict__ z, u8* __restrict__ s,
                         int E, int F,
                         const u32* __restrict__ gin, int ngin,
                         u32* __restrict__ gout, float vth)
{
    u32 part = 0;
    #pragma unroll 1
    for (int i = threadIdx.x; i < ngin; i += NTHR)
        part |= __ldg(&gin[i]);
    u32 anyall = (u32)__syncthreads_or((int)part);
    if (!anyall) return;

    for (int e = blockIdx.x * NTHR + threadIdx.x; e < E; e += NBLK * NTHR) {
        float v = 0.f;
        u32 any = 0;
        #pragma unroll
        for (int t = 0; t < TSTEPS; t++) {
            v += z[t*E + e];
            float sp = (v >= vth) ? 1.f : 0.f;
            v -= v * sp;
            s[t*E + e] = (u8)sp;
            any |= (sp != 0.f);
        }
        if (any) gout[(e % F) >> 4] = 1u;
    }
}

// ---------------------------------------------------------------------------
// FC3 + final IF + mean (always writes out[32,10]).
// ---------------------------------------------------------------------------
__device__ void fc3_stage(const u8* __restrict__ A, const float* __restrict__ W,
                          float* __restrict__ out, const u32* __restrict__ gany,
                          float vth)
{
    int idx = blockIdx.x * NTHR + threadIdx.x;
    if (idx >= 320) return;
    int cls = idx % 10, b = idx / 10;

    u32 anyall = 0;
    #pragma unroll
    for (int i = 0; i < 32; i++) anyall |= __ldg(&gany[i]);

    float m = 0.f;
    if (anyall) {
        const float* wr = W + cls * 512;
        float v = 0.f;
        #pragma unroll 1
        for (int t = 0; t < TSTEPS; t++) {
            const u8* ar = A + (t*BATCH + b) * 512;
            float d = 0.f;
            #pragma unroll 4
            for (int k = 0; k < 512; k += 4) {
                uchar4 av = *reinterpret_cast<const uchar4*>(ar + k);
                float4 wv = *reinterpret_cast<const float4*>(wr + k);
                d = fmaf((float)av.x, wv.x, d); d = fmaf((float)av.y, wv.y, d);
                d = fmaf((float)av.z, wv.z, d); d = fmaf((float)av.w, wv.w, d);
            }
            v += d;
            float sp = (v >= vth) ? 1.f : 0.f;
            v -= v * sp;
            m += sp;
        }
    }
    out[b*10 + cls] = m * (1.f / TSTEPS);
}

// ---------------------------------------------------------------------------
// THE megakernel.
// ---------------------------------------------------------------------------
__global__ __launch_bounds__(NTHR) void snn_mega(
    const float* __restrict__ x,
    const float* __restrict__ w1, const float* __restrict__ b1,
    const float* __restrict__ w2, const float* __restrict__ b2,
    const float* __restrict__ w3, const float* __restrict__ b3,
    const float* __restrict__ w4, const float* __restrict__ b4,
    const float* __restrict__ w5, const float* __restrict__ b5,
    const float* __restrict__ fc1w, const float* __restrict__ fc2w,
    const float* __restrict__ fc3w, float* __restrict__ out)
{
    __shared__ __align__(16) char sm[SMEM_BYTES];
    const int bid = blockIdx.x;

    u32* gany5  = g_gz + 0;
    u32* ganyf1 = g_gz + 8;
    u32* ganyf2 = g_gz + 136;

    // zero gany words (visible after the first barrier)
    if (bid == 0 && threadIdx.x < NGZ) g_gz[threadIdx.x] = 0u;

    // Stage 0: conv1 + IF   (items: 32 imgs x 8 oc-groups)
    for (int item = bid; item < 256; item += NBLK)
        conv1_item(sm, item >> 3, (item & 7) * 16, x, w1, b1, g_s1, g_f1, 13515.f);
    gsync();

    // Stage 1: L2 conv 128->128 4x4 s2 p1, 26->13
    for (int item = bid; item < 256; item += NBLK)
        conv_item<128,128,26,26,13,13,4,4,2,1,4,true>
            (sm, (item & 7) * 16, item >> 3, g_s1, w2, b2, g_s2, g_f1, g_f2,
             nullptr, 71.f);
    gsync();

    // Stage 2: L3 conv 128->192 3x3 s1 p1, 13->13
    for (int item = bid; item < 384; item += NBLK)
        conv_item<128,192,13,13,13,13,3,3,1,1,8,true>
            (sm, (item % 12) * 16, item / 12, g_s2, w3, b3, g_s3, g_f2, g_f3,
             nullptr, 93.f);
    gsync();

    // Stage 3: L4 conv 192->128 3x3 s1 p1, 13->13
    for (int item = bid; item < 256; item += NBLK)
        conv_item<192,128,13,13,13,13,3,3,1,1,8,true>
            (sm, (item & 7) * 16, item >> 3, g_s3, w4, b4, g_s4, g_f3, g_f4,
             nullptr, 144.f);
    gsync();

    // Stage 4: L5 conv 128->128 3x3 s2 p0, 13->6 (ungated, sets gany5)
    for (int item = bid; item < 256; item += NBLK)
        conv_item<128,128,13,13,6,6,3,3,2,0,4,false>
            (sm, (item & 7) * 16, item >> 3, g_s4, w5, b5, g_s5, g_f4, nullptr,
             gany5, 79.f);
    gsync();

    // Stage 5: FC1 gemm [256,4608]x[2048,4608]^T  (ppc=36, 8 groups)
    gemm_stage(sm, g_s5, fc1w, g_zf1, 256, 2048, 4608, gany5, 36, 8);
    gsync();

    // Stage 6: IF on zf1 -> sf1 (+ ganyf1)
    if_stage(g_zf1, g_sf1, 32*2048, 2048, gany5, 8, ganyf1, 2475.f);
    gsync();

    // Stage 7: FC2 gemm [256,2048]x[512,2048]^T  (ppc=1, 128 groups)
    gemm_stage(sm, g_sf1, fc2w, g_zf2, 256, 512, 2048, ganyf1, 1, 128);
    gsync();

    // Stage 8: IF on zf2 -> sf2 (+ ganyf2)
    if_stage(g_zf2, g_sf2, 32*512, 512, ganyf1, 128, ganyf2, 1357.f);
    gsync();

    // Stage 9: FC3 + final IF + mean -> out[32,10]
    fc3_stage(g_sf2, fc3w, out, ganyf2, 388.f);
}

// ---------------------------------------------------------------------------
extern "C" void kernel_launch(void* const* d_in, const int* in_sizes, int n_in,
                              void* d_out, int out_size)
{
    (void)in_sizes; (void)n_in; (void)out_size;
    snn_mega<<<NBLK, NTHR>>>(
        (const float*)d_in[0],
        (const float*)d_in[1],  (const float*)d_in[2],
        (const float*)d_in[3],  (const float*)d_in[4],
        (const float*)d_in[5],  (const float*)d_in[6],
        (const float*)d_in[7],  (const float*)d_in[8],
        (const float*)d_in[9],  (const float*)d_in[10],
        (const float*)d_in[11], (const float*)d_in[12],
        (const float*)d_in[13], (float*)d_out);
}

// round 7
// speedup vs baseline: 1.2117x; 1.2117x over previous
#include <cuda_runtime.h>

// ============================================================================
// CSNN (T=8, B=32) megakernel v2: 256 co-resident blocks (2/SM), 10 stages,
// software grid barriers. Compact sparsity contract: one u8 per (image,
// 16-channel group) carrying 8 timestep bits; producer writes all 16 planes
// of a group at t iff any channel of the group spiked at t. All-zero input
// group -> consumer zero-fills, no spike memory traffic anywhere.
// Layout: [T][B][C][H][W] row-major, n = t*32 + b.
// ============================================================================

#define TSTEPS 8
#define BATCH  32
#define NBLK   256
#define NTHR   256

typedef unsigned char u8;
typedef unsigned int  u32;

// ---------------- static scratch ----------------
__device__ u8    g_s1 [8*32*128*26*26];
__device__ u8    g_s2 [8*32*128*13*13];
__device__ u8    g_s3 [8*32*192*13*13];
__device__ u8    g_s4 [8*32*128*13*13];
__device__ u8    g_s5 [8*32*128*6*6];
__device__ float g_zf1[8*32*2048];
__device__ u8    g_sf1[8*32*2048];
__device__ float g_zf2[8*32*512];
__device__ u8    g_sf2[8*32*512];

// compact flags: u8 per (image b, 16-ch group), bit t = group nonzero at t.
// Rewritten unconditionally by the owning producer block each run.
__device__ u8 g_m1[32*8];
__device__ u8 g_m2[32*8];
__device__ u8 g_m3[32*12];
__device__ u8 g_m4[32*8];

// FC-chain any-flags (zeroed at kernel entry by block 0):
//  gany5 @0 (8 words), ganyf1 @8 (128), ganyf2 @136 (32)
#define NGZ 168
__device__ u32 g_gz[NGZ];

// grid barrier (generation counting; replay-safe)
__device__ u32 g_barcnt;
__device__ u32 g_bargen;

__device__ __forceinline__ void gsync()
{
    __syncthreads();
    if (threadIdx.x == 0) {
        u32 gen = *(volatile u32*)&g_bargen;
        __threadfence();
        if (atomicAdd(&g_barcnt, 1u) == NBLK - 1) {
            g_barcnt = 0;
            __threadfence();
            atomicAdd(&g_bargen, 1u);
        } else {
            while (*(volatile u32*)&g_bargen == gen) { }
        }
    }
    __syncthreads();
}

#define SMEM_BYTES 16896

// ---------------------------------------------------------------------------
// Stage 0: conv1 (1ch,5x5,s1,p1) for one (image b, 16-oc group g); conv done
// ONCE (time-invariant input), IF over T. Gated plane stores + mask byte.
// ---------------------------------------------------------------------------
__device__ void conv1_item(char* smraw, int b, int g,
    const float* __restrict__ x, const float* __restrict__ w,
    const float* __restrict__ bias, u8* __restrict__ s1, u8* __restrict__ m1,
    float vth)
{
    float* sx    = (float*)smraw;            // 900
    float* sw    = sx + 900;                 // 16*28 (padded, float4-aligned)
    u32*   sflag = (u32*)(sw + 16*28);       // 16
    u8*    smask = (u8*)(sflag + 16);        // 676*16
    const int tid = threadIdx.x;
    const int oc0 = g * 16;

    __syncthreads();
    #pragma unroll 1
    for (int i = tid; i < 900; i += NTHR) {
        int r = i / 30, c = i - 30*r;
        float v = 0.f;
        if (r >= 1 && r < 29 && c >= 1 && c < 29)
            v = x[b*784 + (r-1)*28 + (c-1)];
        sx[i] = v;
    }
    #pragma unroll 1
    for (int i = tid; i < 16*28; i += NTHR) {
        int oc = i / 28, k = i - oc*28;
        sw[i] = (k < 25) ? w[(oc0 + oc)*25 + k] : 0.f;
    }
    if (tid < 16) sflag[tid] = 0u;
    __syncthreads();

    float bv[16];
    #pragma unroll
    for (int oc = 0; oc < 16; oc++) bv[oc] = __ldg(&bias[oc0 + oc]);

    #pragma unroll 1
    for (int pos = tid; pos < 676; pos += NTHR) {
        int oy = pos / 26, ox = pos - 26*oy;
        float xv[28];
        #pragma unroll
        for (int ky = 0; ky < 5; ky++)
            #pragma unroll
            for (int kx = 0; kx < 5; kx++)
                xv[ky*5 + kx] = sx[(oy+ky)*30 + ox+kx];
        xv[25] = xv[26] = xv[27] = 0.f;
        #pragma unroll
        for (int oc = 0; oc < 16; oc++) {
            float a = bv[oc];
            #pragma unroll
            for (int q = 0; q < 7; q++) {
                float4 w4 = *reinterpret_cast<const float4*>(&sw[oc*28 + q*4]);
                a = fmaf(xv[q*4+0], w4.x, a);
                a = fmaf(xv[q*4+1], w4.y, a);
                a = fmaf(xv[q*4+2], w4.z, a);
                a = fmaf(xv[q*4+3], w4.w, a);
            }
            float v = 0.f; u32 bits = 0;
            #pragma unroll
            for (int t = 0; t < TSTEPS; t++) {
                v += a;
                float sp = (v >= vth) ? 1.f : 0.f;
                v -= v * sp;
                if (sp != 0.f) bits |= 1u << t;
            }
            smask[pos*16 + oc] = (u8)bits;
            if (bits) atomicOr(&sflag[oc], bits);
        }
    }
    __syncthreads();

    u32 tany = 0;
    #pragma unroll
    for (int oc = 0; oc < 16; oc++) tany |= sflag[oc];
    if (tid == 0) m1[b*8 + g] = (u8)tany;

    if (tany) {
        #pragma unroll 1
        for (int t = 0; t < TSTEPS; t++) {
            if (!((tany >> t) & 1u)) continue;
            for (int i = tid; i < 16*676; i += NTHR) {
                int oc = i / 676, pos = i - oc*676;
                s1[((size_t)(t*BATCH + b)*128 + oc0 + oc)*676 + pos] =
                    (u8)((smask[pos*16 + oc] >> t) & 1u);
            }
        }
    }
}

// ---------------------------------------------------------------------------
// Conv+IF item, layers 2..5 (one 16-oc tile, one image, all timesteps).
// GATED: mask-gated plane stores + mask byte out.   !GATED (L5): write all
// planes always + set global gany word per group.
// ---------------------------------------------------------------------------
template <int CIN, int COUT, int IH, int IW, int OH, int OW,
          int KH, int KW, int S, int PAD, int CC, bool GATED>
__device__ void conv_item(char* smraw, int oc0, int b,
    const u8* __restrict__ in, const float* __restrict__ wgt,
    const float* __restrict__ bias, u8* __restrict__ sout,
    const u8* __restrict__ min_, u8* __restrict__ mout,
    u32* __restrict__ gany, float vth)
{
    constexpr int TC    = 16;
    constexpr int P     = OH * OW;
    constexpr int PIH   = (OH - 1) * S + KH;
    constexpr int PIW   = (OW - 1) * S + KW;
    constexpr int KK    = KH * KW;
    constexpr int KWPAD = (KK + 3) & ~3;
    constexpr int GIN   = CIN / 16;
    constexpr int GOUT  = COUT / 16;
    constexpr int MW    = GIN / 4;

    u32*   s_mw = (u32*)smraw;                    // MW words (<=3)
    float* s_in = (float*)(smraw + 16);           // CC*PIH*PIW
    float* s_w  = s_in + CC*PIH*PIW;              // CC*TC*KWPAD
    const u8* s_mb = (const u8*)s_mw;
    const int tid = threadIdx.x;

    __syncthreads();
    if (tid < MW) s_mw[tid] = ((const u32*)min_)[b*MW + tid];
    __syncthreads();

    u32 allb = 0;
    #pragma unroll
    for (int i = 0; i < MW; i++) allb |= s_mw[i];
    u32 tmask = (allb | (allb >> 8) | (allb >> 16) | (allb >> 24)) & 0xFFu;

    float bi[TC];
    #pragma unroll
    for (int i = 0; i < TC; i++) bi[i] = __ldg(&bias[oc0 + i]);

    if (tmask == 0u) {
        // -------- FLAT PATH: bias-only IF --------
        u32 spb[TC]; u32 tany = 0;
        #pragma unroll
        for (int oc = 0; oc < TC; oc++) {
            float v = 0.f; u32 bits = 0;
            #pragma unroll
            for (int t = 0; t < TSTEPS; t++) {
                v += bi[oc];
                float sp = (v >= vth) ? 1.f : 0.f;
                v -= v * sp;
                if (sp != 0.f) bits |= 1u << t;
            }
            spb[oc] = bits; tany |= bits;
        }
        if (GATED) {
            if (tid == 0) mout[b*GOUT + (oc0 >> 4)] = (u8)tany;
            if (tany) {
                #pragma unroll 1
                for (int t = 0; t < TSTEPS; t++) {
                    if (!((tany >> t) & 1u)) continue;
                    for (int i = tid; i < TC*P; i += NTHR) {
                        int oc = i / P, p = i - oc*P;
                        sout[((size_t)(t*BATCH + b)*COUT + oc0 + oc)*P + p] =
                            (u8)((spb[oc] >> t) & 1u);
                    }
                }
            }
        } else {
            #pragma unroll 1
            for (int i = tid; i < TSTEPS*TC*P; i += NTHR) {
                int t   = i / (TC*P);
                int rem = i - t*(TC*P);
                int oc  = rem / P;
                int p   = rem - oc*P;
                sout[((size_t)(t*BATCH + b)*COUT + oc0 + oc)*P + p] =
                    (u8)((spb[oc] >> t) & 1u);
            }
            if (tany && tid == 0) gany[oc0 >> 4] = 1u;
        }
        return;
    }

    // -------- TILED CONV PATH --------
    const int pos = tid;
    const bool active = pos < P;
    const int oy = pos / OW;
    const int ox = pos - oy * OW;

    float v[TC];
    #pragma unroll
    for (int i = 0; i < TC; i++) v[i] = 0.f;

    u32 tany_acc = 0;
    for (int t = 0; t < TSTEPS; t++) {
        float acc[TC];
        #pragma unroll
        for (int i = 0; i < TC; i++) acc[i] = 0.f;

        if ((tmask >> t) & 1u) {
            #pragma unroll 1
            for (int c0 = 0; c0 < CIN; c0 += CC) {
                if (!((s_mb[c0 >> 4] >> t) & 1u)) continue;

                #pragma unroll 1
                for (int i = tid; i < CC*PIH*PIW; i += NTHR) {
                    int cc = i / (PIH*PIW);
                    int pp = i - cc*(PIH*PIW);
                    int py = pp / PIW;
                    int px = pp - py*PIW;
                    int iy = py - PAD, ix = px - PAD;
                    float val = 0.f;
                    if (iy >= 0 && iy < IH && ix >= 0 && ix < IW)
                        val = (float)in[((size_t)(t*BATCH + b)*CIN + c0 + cc)*(IH*IW)
                                        + iy*IW + ix];
                    s_in[cc*(PIH*PIW) + pp] = val;
                }
                #pragma unroll 1
                for (int i = tid; i < CC*TC*KK; i += NTHR) {
                    int cc  = i / (TC*KK);
                    int rem = i - cc*(TC*KK);
                    int oc  = rem / KK;
                    int k   = rem - oc*KK;
                    s_w[(cc*TC + oc)*KWPAD + k] = wgt[((oc0 + oc)*CIN + c0 + cc)*KK + k];
                }
                __syncthreads();
                if (active) {
                    #pragma unroll
                    for (int cc = 0; cc < CC; cc++) {
                        float xin[KK];
                        #pragma unroll
                        for (int ky = 0; ky < KH; ky++)
                            #pragma unroll
                            for (int kx = 0; kx < KW; kx++)
                                xin[ky*KW + kx] =
                                    s_in[cc*(PIH*PIW) + (oy*S + ky)*PIW + ox*S + kx];
                        #pragma unroll
                        for (int oc = 0; oc < TC; oc++) {
                            float wv[KWPAD];
                            #pragma unroll
                            for (int q = 0; q < KWPAD/4; q++) {
                                float4 v4 = *reinterpret_cast<const float4*>(
                                    &s_w[(cc*TC + oc)*KWPAD + q*4]);
                                wv[q*4+0] = v4.x; wv[q*4+1] = v4.y;
                                wv[q*4+2] = v4.z; wv[q*4+3] = v4.w;
                            }
                            float a = acc[oc];
                            #pragma unroll
                            for (int k = 0; k < KK; k++)
                                a = fmaf(xin[k], wv[k], a);
                            acc[oc] = a;
                        }
                    }
                }
                __syncthreads();
            }
        }

        u32 myspk = 0;
        if (active) {
            #pragma unroll
            for (int oc = 0; oc < TC; oc++) {
                v[oc] += acc[oc] + bi[oc];
                float sp = (v[oc] >= vth) ? 1.f : 0.f;
                v[oc] -= v[oc] * sp;
                if (sp != 0.f) myspk |= 1u << oc;
            }
        }
        u32 bm = (u32)__syncthreads_or((int)myspk);

        if (GATED) {
            if (bm) {
                tany_acc |= 1u << t;
                if (active) {
                    #pragma unroll
                    for (int oc = 0; oc < TC; oc++)
                        sout[((size_t)(t*BATCH + b)*COUT + oc0 + oc)*P + pos] =
                            (u8)((myspk >> oc) & 1u);
                }
            }
        } else {
            if (active) {
                #pragma unroll
                for (int oc = 0; oc < TC; oc++)
                    sout[((size_t)(t*BATCH + b)*COUT + oc0 + oc)*P + pos] =
                        (u8)((myspk >> oc) & 1u);
            }
            if (bm && tid == 0) gany[oc0 >> 4] = 1u;
        }
    }
    if (GATED && tid == 0) mout[b*GOUT + (oc0 >> 4)] = (u8)tany_acc;
}

// ---------------------------------------------------------------------------
// GEMM stage: C[M,N] = A[M,K](u8) * B[N,K]^T, 64x64x16 tiles.
// All-zero input (gany words) -> exit (paired IF stage checks same words).
// ---------------------------------------------------------------------------
__device__ void gemm_stage(char* smraw,
    const u8* __restrict__ A, const float* __restrict__ B,
    float* __restrict__ C, int M, int N, int K,
    const u32* __restrict__ gany, int ppc, int ngrp)
{
    float* As    = (float*)smraw;            // 16*64
    float* Bs    = As + 16*64;               // 16*64
    u32*   s_any = (u32*)(Bs + 16*64);       // up to 128
    const int tid = threadIdx.x;

    __syncthreads();
    u32 part = 0;
    #pragma unroll 1
    for (int i = tid; i < ngrp; i += NTHR) {
        u32 g = __ldg(&gany[i]);
        s_any[i] = g;
        part |= g;
    }
    u32 anyall = (u32)__syncthreads_or((int)part);
    if (!anyall) return;

    const int tm = tid >> 4, tn = tid & 15;
    const int r = tid >> 2, q = (tid & 3) << 2;
    const int ntx = N / 64;
    const int ntiles = ntx * (M / 64);

    for (int tile = blockIdx.x; tile < ntiles; tile += NBLK) {
        int n0 = (tile % ntx) * 64;
        int m0 = (tile / ntx) * 64;

        float c[4][4];
        #pragma unroll
        for (int i = 0; i < 4; i++)
            #pragma unroll
            for (int j = 0; j < 4; j++) c[i][j] = 0.f;

        for (int k0 = 0; k0 < K; k0 += 16) {
            int g1 = (k0 / ppc) >> 4;
            int g2 = ((k0 + 15) / ppc) >> 4;
            if (!(s_any[g1] | s_any[g2])) continue;

            uchar4 av = *reinterpret_cast<const uchar4*>(&A[(m0 + r) * K + k0 + q]);
            As[(q+0)*64 + r] = (float)av.x; As[(q+1)*64 + r] = (float)av.y;
            As[(q+2)*64 + r] = (float)av.z; As[(q+3)*64 + r] = (float)av.w;
            int f = av.x | av.y | av.z | av.w;
            if (__syncthreads_or(f)) {
                float4 bv = *reinterpret_cast<const float4*>(&B[(n0 + r) * K + k0 + q]);
                Bs[(q+0)*64 + r] = bv.x; Bs[(q+1)*64 + r] = bv.y;
                Bs[(q+2)*64 + r] = bv.z; Bs[(q+3)*64 + r] = bv.w;
                __syncthreads();
                #pragma unroll
                for (int kk = 0; kk < 16; kk++) {
                    float4 a = *reinterpret_cast<const float4*>(&As[kk*64 + tm*4]);
                    float4 b = *reinterpret_cast<const float4*>(&Bs[kk*64 + tn*4]);
                    c[0][0] = fmaf(a.x, b.x, c[0][0]); c[0][1] = fmaf(a.x, b.y, c[0][1]);
                    c[0][2] = fmaf(a.x, b.z, c[0][2]); c[0][3] = fmaf(a.x, b.w, c[0][3]);
                    c[1][0] = fmaf(a.y, b.x, c[1][0]); c[1][1] = fmaf(a.y, b.y, c[1][1]);
                    c[1][2] = fmaf(a.y, b.z, c[1][2]); c[1][3] = fmaf(a.y, b.w, c[1][3]);
                    c[2][0] = fmaf(a.z, b.x, c[2][0]); c[2][1] = fmaf(a.z, b.y, c[2][1]);
                    c[2][2] = fmaf(a.z, b.z, c[2][2]); c[2][3] = fmaf(a.z, b.w, c[2][3]);
                    c[3][0] = fmaf(a.w, b.x, c[3][0]); c[3][1] = fmaf(a.w, b.y, c[3][1]);
                    c[3][2] = fmaf(a.w, b.z, c[3][2]); c[3][3] = fmaf(a.w, b.w, c[3][3]);
                }
                __syncthreads();
            }
        }
        #pragma unroll
        for (int i = 0; i < 4; i++)
            #pragma unroll
            for (int j = 0; j < 4; j++)
                C[(m0 + tm*4 + i) * N + n0 + tn*4 + j] = c[i][j];
    }
}

// ---------------------------------------------------------------------------
// IF stage for FC layers (exit when producer's input flags all zero).
// ---------------------------------------------------------------------------
__device__ void if_stage(const float* __restrict__ z, u8* __restrict__ s,
                         int E, int F,
                         const u32* __restrict__ gin, int ngin,
                         u32* __restrict__ gout, float vth)
{
    u32 part = 0;
    #pragma unroll 1
    for (int i = threadIdx.x; i < ngin; i += NTHR)
        part |= __ldg(&gin[i]);
    u32 anyall = (u32)__syncthreads_or((int)part);
    if (!anyall) return;

    for (int e = blockIdx.x * NTHR + threadIdx.x; e < E; e += NBLK * NTHR) {
        float v = 0.f;
        u32 any = 0;
        #pragma unroll
        for (int t = 0; t < TSTEPS; t++) {
            v += z[t*E + e];
            float sp = (v >= vth) ? 1.f : 0.f;
            v -= v * sp;
            s[t*E + e] = (u8)sp;
            any |= (sp != 0.f);
        }
        if (any) gout[(e % F) >> 4] = 1u;
    }
}

// ---------------------------------------------------------------------------
// FC3 + final IF + mean (always writes out[32,10]).
// ---------------------------------------------------------------------------
__device__ void fc3_stage(const u8* __restrict__ A, const float* __restrict__ W,
                          float* __restrict__ out, const u32* __restrict__ gany,
                          float vth)
{
    int idx = blockIdx.x * NTHR + threadIdx.x;
    if (idx >= 320) return;
    int cls = idx % 10, b = idx / 10;

    u32 anyall = 0;
    #pragma unroll
    for (int i = 0; i < 32; i++) anyall |= __ldg(&gany[i]);

    float m = 0.f;
    if (anyall) {
        const float* wr = W + cls * 512;
        float v = 0.f;
        #pragma unroll 1
        for (int t = 0; t < TSTEPS; t++) {
            const u8* ar = A + (t*BATCH + b) * 512;
            float d = 0.f;
            #pragma unroll 4
            for (int k = 0; k < 512; k += 4) {
                uchar4 av = *reinterpret_cast<const uchar4*>(ar + k);
                float4 wv = *reinterpret_cast<const float4*>(wr + k);
                d = fmaf((float)av.x, wv.x, d); d = fmaf((float)av.y, wv.y, d);
                d = fmaf((float)av.z, wv.z, d); d = fmaf((float)av.w, wv.w, d);
            }
            v += d;
            float sp = (v >= vth) ? 1.f : 0.f;
            v -= v * sp;
            m += sp;
        }
    }
    out[b*10 + cls] = m * (1.f / TSTEPS);
}

// ---------------------------------------------------------------------------
// THE megakernel (v2: 256 blocks, 2/SM).
// ---------------------------------------------------------------------------
__global__ __launch_bounds__(NTHR, 2) void snn_mega(
    const float* __restrict__ x,
    const float* __restrict__ w1, const float* __restrict__ b1,
    const float* __restrict__ w2, const float* __restrict__ b2,
    const float* __restrict__ w3, const float* __restrict__ b3,
    const float* __restrict__ w4, const float* __restrict__ b4,
    const float* __restrict__ w5, const float* __restrict__ b5,
    const float* __restrict__ fc1w, const float* __restrict__ fc2w,
    const float* __restrict__ fc3w, float* __restrict__ out)
{
    __shared__ __align__(16) char sm[SMEM_BYTES];
    const int bid = blockIdx.x;

    u32* gany5  = g_gz + 0;
    u32* ganyf1 = g_gz + 8;
    u32* ganyf2 = g_gz + 136;

    if (bid == 0 && threadIdx.x < NGZ) g_gz[threadIdx.x] = 0u;

    // Stage 0: conv1 + IF  (256 items: b*8 + g)
    conv1_item(sm, bid >> 3, bid & 7, x, w1, b1, g_s1, g_m1, 13515.f);
    gsync();

    // Stage 1: L2 conv 128->128 4x4 s2 p1, 26->13  (256 items)
    conv_item<128,128,26,26,13,13,4,4,2,1,4,true>
        (sm, (bid & 7) * 16, bid >> 3, g_s1, w2, b2, g_s2, g_m1, g_m2,
         nullptr, 71.f);
    gsync();

    // Stage 2: L3 conv 128->192 3x3 s1 p1  (384 items)
    for (int item = bid; item < 384; item += NBLK)
        conv_item<128,192,13,13,13,13,3,3,1,1,8,true>
            (sm, (item % 12) * 16, item / 12, g_s2, w3, b3, g_s3, g_m2, g_m3,
             nullptr, 93.f);
    gsync();

    // Stage 3: L4 conv 192->128 3x3 s1 p1  (256 items)
    conv_item<192,128,13,13,13,13,3,3,1,1,8,true>
        (sm, (bid & 7) * 16, bid >> 3, g_s3, w4, b4, g_s4, g_m3, g_m4,
         nullptr, 144.f);
    gsync();

    // Stage 4: L5 conv 128->128 3x3 s2 p0, 13->6 (ungated, sets gany5)
    conv_item<128,128,13,13,6,6,3,3,2,0,4,false>
        (sm, (bid & 7) * 16, bid >> 3, g_s4, w5, b5, g_s5, g_m4, nullptr,
         gany5, 79.f);
    gsync();

    // Stage 5: FC1 gemm [256,4608]x[2048,4608]^T  (ppc=36, 8 groups)
    gemm_stage(sm, g_s5, fc1w, g_zf1, 256, 2048, 4608, gany5, 36, 8);
    gsync();

    // Stage 6: IF zf1 -> sf1 (+ ganyf1)
    if_stage(g_zf1, g_sf1, 32*2048, 2048, gany5, 8, ganyf1, 2475.f);
    gsync();

    // Stage 7: FC2 gemm [256,2048]x[512,2048]^T  (ppc=1, 128 groups)
    gemm_stage(sm, g_sf1, fc2w, g_zf2, 256, 512, 2048, ganyf1, 1, 128);
    gsync();

    // Stage 8: IF zf2 -> sf2 (+ ganyf2)
    if_stage(g_zf2, g_sf2, 32*512, 512, ganyf1, 128, ganyf2, 1357.f);
    gsync();

    // Stage 9: FC3 + final IF + mean -> out[32,10]
    fc3_stage(g_sf2, fc3w, out, ganyf2, 388.f);
}

// ---------------------------------------------------------------------------
extern "C" void kernel_launch(void* const* d_in, const int* in_sizes, int n_in,
                              void* d_out, int out_size)
{
    (void)in_sizes; (void)n_in; (void)out_size;
    snn_mega<<<NBLK, NTHR>>>(
        (const float*)d_in[0],
        (const float*)d_in[1],  (const float*)d_in[2],
        (const float*)d_in[3],  (const float*)d_in[4],
        (const float*)d_in[5],  (const float*)d_in[6],
        (const float*)d_in[7],  (const float*)d_in[8],
        (const float*)d_in[9],  (const float*)d_in[10],
        (const float*)d_in[11], (const float*)d_in[12],
        (const float*)d_in[13], (float*)d_out);
}

// round 8
// speedup vs baseline: 2.9959x; 2.4725x over previous
#include <cuda_runtime.h>

// ============================================================================
// CSNN (T=8, B=32). Two kernels:
//  A) conv1+IF (real work; input is time-invariant so conv is done once),
//     writing compact masks m1 (u8 per (image, 16-oc group), bit t) and
//     spike planes only for flagged (t, group).
//  B) tail: uniform zero-proof — if m1==0 and bias-only IF of L2..L5 yields
//     no spikes, the entire rest of the network is exactly zero -> write out=0.
//     Otherwise: full staged fallback (conv/gemm/IF with grid barriers).
// Layout: [T][B][C][H][W] row-major, n = t*32 + b.
// ============================================================================

#define TSTEPS 8
#define BATCH  32
#define NBLK   256
#define NTHR   256

typedef unsigned char u8;
typedef unsigned int  u32;

// ---------------- static scratch ----------------
__device__ u8    g_s1 [8*32*128*26*26];
__device__ u8    g_s2 [8*32*128*13*13];
__device__ u8    g_s3 [8*32*192*13*13];
__device__ u8    g_s4 [8*32*128*13*13];
__device__ u8    g_s5 [8*32*128*6*6];
__device__ float g_zf1[8*32*2048];
__device__ u8    g_sf1[8*32*2048];
__device__ float g_zf2[8*32*512];
__device__ u8    g_sf2[8*32*512];

// compact masks: u8 per (image b, 16-ch group), bit t = group nonzero at t
__device__ u8 g_m1[32*8];
__device__ u8 g_m2[32*8];
__device__ u8 g_m3[32*12];
__device__ u8 g_m4[32*8];

// FC-chain any-flags (zeroed in fallback path only)
#define NGZ 168
__device__ u32 g_gz[NGZ];

// grid barrier (generation counting; replay-safe)
__device__ u32 g_barcnt;
__device__ u32 g_bargen;

__device__ __forceinline__ void gsync()
{
    __syncthreads();
    if (threadIdx.x == 0) {
        u32 gen = *(volatile u32*)&g_bargen;
        __threadfence();
        if (atomicAdd(&g_barcnt, 1u) == NBLK - 1) {
            g_barcnt = 0;
            __threadfence();
            atomicAdd(&g_bargen, 1u);
        } else {
            while (*(volatile u32*)&g_bargen == gen) { }
        }
    }
    __syncthreads();
}

#define SMEM_BYTES 16896

// ---------------------------------------------------------------------------
// Kernel A: conv1 (1ch,5x5,s1,p1) + IF, one (image b, 16-oc group g) per block.
// ---------------------------------------------------------------------------
__global__ __launch_bounds__(NTHR, 2) void conv1_if(
    const float* __restrict__ x, const float* __restrict__ w,
    const float* __restrict__ bias, u8* __restrict__ s1, u8* __restrict__ m1,
    float vth)
{
    __shared__ float sx[900];
    __shared__ float sw[16*28];
    __shared__ u32   sflag[16];
    __shared__ u8    smask[676*16];
    const int tid = threadIdx.x;
    const int b   = blockIdx.x >> 3;
    const int g   = blockIdx.x & 7;
    const int oc0 = g * 16;

    #pragma unroll 1
    for (int i = tid; i < 900; i += NTHR) {
        int r = i / 30, c = i - 30*r;
        float v = 0.f;
        if (r >= 1 && r < 29 && c >= 1 && c < 29)
            v = x[b*784 + (r-1)*28 + (c-1)];
        sx[i] = v;
    }
    #pragma unroll 1
    for (int i = tid; i < 16*28; i += NTHR) {
        int oc = i / 28, k = i - oc*28;
        sw[i] = (k < 25) ? w[(oc0 + oc)*25 + k] : 0.f;
    }
    if (tid < 16) sflag[tid] = 0u;
    __syncthreads();

    float bv[16];
    #pragma unroll
    for (int oc = 0; oc < 16; oc++) bv[oc] = __ldg(&bias[oc0 + oc]);

    #pragma unroll 1
    for (int pos = tid; pos < 676; pos += NTHR) {
        int oy = pos / 26, ox = pos - 26*oy;
        float xv[28];
        #pragma unroll
        for (int ky = 0; ky < 5; ky++)
            #pragma unroll
            for (int kx = 0; kx < 5; kx++)
                xv[ky*5 + kx] = sx[(oy+ky)*30 + ox+kx];
        xv[25] = xv[26] = xv[27] = 0.f;
        #pragma unroll
        for (int oc = 0; oc < 16; oc++) {
            float a = bv[oc];
            #pragma unroll
            for (int q = 0; q < 7; q++) {
                float4 w4 = *reinterpret_cast<const float4*>(&sw[oc*28 + q*4]);
                a = fmaf(xv[q*4+0], w4.x, a);
                a = fmaf(xv[q*4+1], w4.y, a);
                a = fmaf(xv[q*4+2], w4.z, a);
                a = fmaf(xv[q*4+3], w4.w, a);
            }
            float v = 0.f; u32 bits = 0;
            #pragma unroll
            for (int t = 0; t < TSTEPS; t++) {
                v += a;
                float sp = (v >= vth) ? 1.f : 0.f;
                v -= v * sp;
                if (sp != 0.f) bits |= 1u << t;
            }
            smask[pos*16 + oc] = (u8)bits;
            if (bits) atomicOr(&sflag[oc], bits);
        }
    }
    __syncthreads();

    u32 tany = 0;
    #pragma unroll
    for (int oc = 0; oc < 16; oc++) tany |= sflag[oc];
    if (tid == 0) m1[b*8 + g] = (u8)tany;

    if (tany) {
        #pragma unroll 1
        for (int t = 0; t < TSTEPS; t++) {
            if (!((tany >> t) & 1u)) continue;
            for (int i = tid; i < 16*676; i += NTHR) {
                int oc = i / 676, pos = i - oc*676;
                s1[((size_t)(t*BATCH + b)*128 + oc0 + oc)*676 + pos] =
                    (u8)((smask[pos*16 + oc] >> t) & 1u);
            }
        }
    }
}

// ---------------------------------------------------------------------------
// Fallback machinery (used only when the network is provably non-zero).
// ---------------------------------------------------------------------------
template <int CIN, int COUT, int IH, int IW, int OH, int OW,
          int KH, int KW, int S, int PAD, int CC, bool GATED>
__device__ void conv_item(char* smraw, int oc0, int b,
    const u8* __restrict__ in, const float* __restrict__ wgt,
    const float* __restrict__ bias, u8* __restrict__ sout,
    const u8* __restrict__ min_, u8* __restrict__ mout,
    u32* __restrict__ gany, float vth)
{
    constexpr int TC    = 16;
    constexpr int P     = OH * OW;
    constexpr int PIH   = (OH - 1) * S + KH;
    constexpr int PIW   = (OW - 1) * S + KW;
    constexpr int KK    = KH * KW;
    constexpr int KWPAD = (KK + 3) & ~3;
    constexpr int GIN   = CIN / 16;
    constexpr int GOUT  = COUT / 16;
    constexpr int MW    = GIN / 4;

    u32*   s_mw = (u32*)smraw;
    float* s_in = (float*)(smraw + 16);
    float* s_w  = s_in + CC*PIH*PIW;
    const u8* s_mb = (const u8*)s_mw;
    const int tid = threadIdx.x;

    __syncthreads();
    if (tid < MW) s_mw[tid] = ((const u32*)min_)[b*MW + tid];
    __syncthreads();

    u32 allb = 0;
    #pragma unroll
    for (int i = 0; i < MW; i++) allb |= s_mw[i];
    u32 tmask = (allb | (allb >> 8) | (allb >> 16) | (allb >> 24)) & 0xFFu;

    float bi[TC];
    #pragma unroll
    for (int i = 0; i < TC; i++) bi[i] = __ldg(&bias[oc0 + i]);

    if (tmask == 0u) {
        u32 spb[TC]; u32 tany = 0;
        #pragma unroll
        for (int oc = 0; oc < TC; oc++) {
            float v = 0.f; u32 bits = 0;
            #pragma unroll
            for (int t = 0; t < TSTEPS; t++) {
                v += bi[oc];
                float sp = (v >= vth) ? 1.f : 0.f;
                v -= v * sp;
                if (sp != 0.f) bits |= 1u << t;
            }
            spb[oc] = bits; tany |= bits;
        }
        if (GATED) {
            if (tid == 0) mout[b*GOUT + (oc0 >> 4)] = (u8)tany;
            if (tany) {
                #pragma unroll 1
                for (int t = 0; t < TSTEPS; t++) {
                    if (!((tany >> t) & 1u)) continue;
                    for (int i = tid; i < TC*P; i += NTHR) {
                        int oc = i / P, p = i - oc*P;
                        sout[((size_t)(t*BATCH + b)*COUT + oc0 + oc)*P + p] =
                            (u8)((spb[oc] >> t) & 1u);
                    }
                }
            }
        } else {
            #pragma unroll 1
            for (int i = tid; i < TSTEPS*TC*P; i += NTHR) {
                int t   = i / (TC*P);
                int rem = i - t*(TC*P);
                int oc  = rem / P;
                int p   = rem - oc*P;
                sout[((size_t)(t*BATCH + b)*COUT + oc0 + oc)*P + p] =
                    (u8)((spb[oc] >> t) & 1u);
            }
            if (tany && tid == 0) gany[oc0 >> 4] = 1u;
        }
        return;
    }

    const int pos = tid;
    const bool active = pos < P;
    const int oy = pos / OW;
    const int ox = pos - oy * OW;

    float v[TC];
    #pragma unroll
    for (int i = 0; i < TC; i++) v[i] = 0.f;

    u32 tany_acc = 0;
    for (int t = 0; t < TSTEPS; t++) {
        float acc[TC];
        #pragma unroll
        for (int i = 0; i < TC; i++) acc[i] = 0.f;

        if ((tmask >> t) & 1u) {
            #pragma unroll 1
            for (int c0 = 0; c0 < CIN; c0 += CC) {
                if (!((s_mb[c0 >> 4] >> t) & 1u)) continue;

                #pragma unroll 1
                for (int i = tid; i < CC*PIH*PIW; i += NTHR) {
                    int cc = i / (PIH*PIW);
                    int pp = i - cc*(PIH*PIW);
                    int py = pp / PIW;
                    int px = pp - py*PIW;
                    int iy = py - PAD, ix = px - PAD;
                    float val = 0.f;
                    if (iy >= 0 && iy < IH && ix >= 0 && ix < IW)
                        val = (float)in[((size_t)(t*BATCH + b)*CIN + c0 + cc)*(IH*IW)
                                        + iy*IW + ix];
                    s_in[cc*(PIH*PIW) + pp] = val;
                }
                #pragma unroll 1
                for (int i = tid; i < CC*TC*KK; i += NTHR) {
                    int cc  = i / (TC*KK);
                    int rem = i - cc*(TC*KK);
                    int oc  = rem / KK;
                    int k   = rem - oc*KK;
                    s_w[(cc*TC + oc)*KWPAD + k] = wgt[((oc0 + oc)*CIN + c0 + cc)*KK + k];
                }
                __syncthreads();
                if (active) {
                    #pragma unroll
                    for (int cc = 0; cc < CC; cc++) {
                        float xin[KK];
                        #pragma unroll
                        for (int ky = 0; ky < KH; ky++)
                            #pragma unroll
                            for (int kx = 0; kx < KW; kx++)
                                xin[ky*KW + kx] =
                                    s_in[cc*(PIH*PIW) + (oy*S + ky)*PIW + ox*S + kx];
                        #pragma unroll
                        for (int oc = 0; oc < TC; oc++) {
                            float wv[KWPAD];
                            #pragma unroll
                            for (int q = 0; q < KWPAD/4; q++) {
                                float4 v4 = *reinterpret_cast<const float4*>(
                                    &s_w[(cc*TC + oc)*KWPAD + q*4]);
                                wv[q*4+0] = v4.x; wv[q*4+1] = v4.y;
                                wv[q*4+2] = v4.z; wv[q*4+3] = v4.w;
                            }
                            float a = acc[oc];
                            #pragma unroll
                            for (int k = 0; k < KK; k++)
                                a = fmaf(xin[k], wv[k], a);
                            acc[oc] = a;
                        }
                    }
                }
                __syncthreads();
            }
        }

        u32 myspk = 0;
        if (active) {
            #pragma unroll
            for (int oc = 0; oc < TC; oc++) {
                v[oc] += acc[oc] + bi[oc];
                float sp = (v[oc] >= vth) ? 1.f : 0.f;
                v[oc] -= v[oc] * sp;
                if (sp != 0.f) myspk |= 1u << oc;
            }
        }
        u32 bm = (u32)__syncthreads_or((int)myspk);

        if (GATED) {
            if (bm) {
                tany_acc |= 1u << t;
                if (active) {
                    #pragma unroll
                    for (int oc = 0; oc < TC; oc++)
                        sout[((size_t)(t*BATCH + b)*COUT + oc0 + oc)*P + pos] =
                            (u8)((myspk >> oc) & 1u);
                }
            }
        } else {
            if (active) {
                #pragma unroll
                for (int oc = 0; oc < TC; oc++)
                    sout[((size_t)(t*BATCH + b)*COUT + oc0 + oc)*P + pos] =
                        (u8)((myspk >> oc) & 1u);
            }
            if (bm && tid == 0) gany[oc0 >> 4] = 1u;
        }
    }
    if (GATED && tid == 0) mout[b*GOUT + (oc0 >> 4)] = (u8)tany_acc;
}

__device__ void gemm_stage(char* smraw,
    const u8* __restrict__ A, const float* __restrict__ B,
    float* __restrict__ C, int M, int N, int K,
    const u32* __restrict__ gany, int ppc, int ngrp)
{
    float* As    = (float*)smraw;
    float* Bs    = As + 16*64;
    u32*   s_any = (u32*)(Bs + 16*64);
    const int tid = threadIdx.x;

    __syncthreads();
    u32 part = 0;
    #pragma unroll 1
    for (int i = tid; i < ngrp; i += NTHR) {
        u32 g = __ldg(&gany[i]);
        s_any[i] = g;
        part |= g;
    }
    u32 anyall = (u32)__syncthreads_or((int)part);
    if (!anyall) return;

    const int tm = tid >> 4, tn = tid & 15;
    const int r = tid >> 2, q = (tid & 3) << 2;
    const int ntx = N / 64;
    const int ntiles = ntx * (M / 64);

    for (int tile = blockIdx.x; tile < ntiles; tile += NBLK) {
        int n0 = (tile % ntx) * 64;
        int m0 = (tile / ntx) * 64;

        float c[4][4];
        #pragma unroll
        for (int i = 0; i < 4; i++)
            #pragma unroll
            for (int j = 0; j < 4; j++) c[i][j] = 0.f;

        for (int k0 = 0; k0 < K; k0 += 16) {
            int g1 = (k0 / ppc) >> 4;
            int g2 = ((k0 + 15) / ppc) >> 4;
            if (!(s_any[g1] | s_any[g2])) continue;

            uchar4 av = *reinterpret_cast<const uchar4*>(&A[(m0 + r) * K + k0 + q]);
            As[(q+0)*64 + r] = (float)av.x; As[(q+1)*64 + r] = (float)av.y;
            As[(q+2)*64 + r] = (float)av.z; As[(q+3)*64 + r] = (float)av.w;
            int f = av.x | av.y | av.z | av.w;
            if (__syncthreads_or(f)) {
                float4 bv = *reinterpret_cast<const float4*>(&B[(n0 + r) * K + k0 + q]);
                Bs[(q+0)*64 + r] = bv.x; Bs[(q+1)*64 + r] = bv.y;
                Bs[(q+2)*64 + r] = bv.z; Bs[(q+3)*64 + r] = bv.w;
                __syncthreads();
                #pragma unroll
                for (int kk = 0; kk < 16; kk++) {
                    float4 a = *reinterpret_cast<const float4*>(&As[kk*64 + tm*4]);
                    float4 b = *reinterpret_cast<const float4*>(&Bs[kk*64 + tn*4]);
                    c[0][0] = fmaf(a.x, b.x, c[0][0]); c[0][1] = fmaf(a.x, b.y, c[0][1]);
                    c[0][2] = fmaf(a.x, b.z, c[0][2]); c[0][3] = fmaf(a.x, b.w, c[0][3]);
                    c[1][0] = fmaf(a.y, b.x, c[1][0]); c[1][1] = fmaf(a.y, b.y, c[1][1]);
                    c[1][2] = fmaf(a.y, b.z, c[1][2]); c[1][3] = fmaf(a.y, b.w, c[1][3]);
                    c[2][0] = fmaf(a.z, b.x, c[2][0]); c[2][1] = fmaf(a.z, b.y, c[2][1]);
                    c[2][2] = fmaf(a.z, b.z, c[2][2]); c[2][3] = fmaf(a.z, b.w, c[2][3]);
                    c[3][0] = fmaf(a.w, b.x, c[3][0]); c[3][1] = fmaf(a.w, b.y, c[3][1]);
                    c[3][2] = fmaf(a.w, b.z, c[3][2]); c[3][3] = fmaf(a.w, b.w, c[3][3]);
                }
                __syncthreads();
            }
        }
        #pragma unroll
        for (int i = 0; i < 4; i++)
            #pragma unroll
            for (int j = 0; j < 4; j++)
                C[(m0 + tm*4 + i) * N + n0 + tn*4 + j] = c[i][j];
    }
}

__device__ void if_stage(const float* __restrict__ z, u8* __restrict__ s,
                         int E, int F,
                         const u32* __restrict__ gin, int ngin,
                         u32* __restrict__ gout, float vth)
{
    u32 part = 0;
    #pragma unroll 1
    for (int i = threadIdx.x; i < ngin; i += NTHR)
        part |= __ldg(&gin[i]);
    u32 anyall = (u32)__syncthreads_or((int)part);
    if (!anyall) return;

    for (int e = blockIdx.x * NTHR + threadIdx.x; e < E; e += NBLK * NTHR) {
        float v = 0.f;
        u32 any = 0;
        #pragma unroll
        for (int t = 0; t < TSTEPS; t++) {
            v += z[t*E + e];
            float sp = (v >= vth) ? 1.f : 0.f;
            v -= v * sp;
            s[t*E + e] = (u8)sp;
            any |= (sp != 0.f);
        }
        if (any) gout[(e % F) >> 4] = 1u;
    }
}

__device__ void fc3_stage(const u8* __restrict__ A, const float* __restrict__ W,
                          float* __restrict__ out, const u32* __restrict__ gany,
                          float vth)
{
    int idx = blockIdx.x * NTHR + threadIdx.x;
    if (idx >= 320) return;
    int cls = idx % 10, b = idx / 10;

    u32 anyall = 0;
    #pragma unroll
    for (int i = 0; i < 32; i++) anyall |= __ldg(&gany[i]);

    float m = 0.f;
    if (anyall) {
        const float* wr = W + cls * 512;
        float v = 0.f;
        #pragma unroll 1
        for (int t = 0; t < TSTEPS; t++) {
            const u8* ar = A + (t*BATCH + b) * 512;
            float d = 0.f;
            #pragma unroll 4
            for (int k = 0; k < 512; k += 4) {
                uchar4 av = *reinterpret_cast<const uchar4*>(ar + k);
                float4 wv = *reinterpret_cast<const float4*>(wr + k);
                d = fmaf((float)av.x, wv.x, d); d = fmaf((float)av.y, wv.y, d);
                d = fmaf((float)av.z, wv.z, d); d = fmaf((float)av.w, wv.w, d);
            }
            v += d;
            float sp = (v >= vth) ? 1.f : 0.f;
            v -= v * sp;
            m += sp;
        }
    }
    out[b*10 + cls] = m * (1.f / TSTEPS);
}

// ---------------------------------------------------------------------------
// Helper: bias-only IF "would any channel spike" bitmask for one thread's ch.
// ---------------------------------------------------------------------------
__device__ __forceinline__ u32 bias_if_bits(float bv, float vth)
{
    float v = 0.f; u32 bits = 0;
    #pragma unroll
    for (int t = 0; t < TSTEPS; t++) {
        v += bv;
        float sp = (v >= vth) ? 1.f : 0.f;
        v -= v * sp;
        if (sp != 0.f) bits |= 1u << t;
    }
    return bits;
}

// ---------------------------------------------------------------------------
// Kernel B: tail. Uniform zero-proof, else full staged fallback.
// ---------------------------------------------------------------------------
__global__ __launch_bounds__(NTHR, 2) void snn_tail(
    const float* __restrict__ w2, const float* __restrict__ b2,
    const float* __restrict__ w3, const float* __restrict__ b3,
    const float* __restrict__ w4, const float* __restrict__ b4,
    const float* __restrict__ w5, const float* __restrict__ b5,
    const float* __restrict__ fc1w, const float* __restrict__ fc2w,
    const float* __restrict__ fc3w, float* __restrict__ out)
{
    __shared__ __align__(16) char sm[SMEM_BYTES];
    const int bid = blockIdx.x;
    const int tid = threadIdx.x;

    // ---- uniform zero-proof ----
    u32 p1 = 0;
    if (tid < 64) p1 = ((const u32*)g_m1)[tid];
    u32 any1 = (u32)__syncthreads_or((int)p1);

    u32 pb = 0;
    if (tid < 128) pb = bias_if_bits(__ldg(&b2[tid]),  71.f);
    u32 any2 = (u32)__syncthreads_or((int)pb);

    pb = 0;
    if (tid < 192) pb = bias_if_bits(__ldg(&b3[tid]),  93.f);
    u32 any3 = (u32)__syncthreads_or((int)pb);

    pb = 0;
    if (tid < 128) pb = bias_if_bits(__ldg(&b4[tid]), 144.f);
    u32 any4 = (u32)__syncthreads_or((int)pb);

    pb = 0;
    if (tid < 128) pb = bias_if_bits(__ldg(&b5[tid]),  79.f);
    u32 any5 = (u32)__syncthreads_or((int)pb);

    if (!(any1 | any2 | any3 | any4 | any5)) {
        // entire network provably zero (FCs have no bias)
        if (bid == 0)
            for (int i = tid; i < 320; i += NTHR) out[i] = 0.f;
        return;
    }

    // ---- full staged fallback (dense / partially-dense data) ----
    u32* gany5  = g_gz + 0;
    u32* ganyf1 = g_gz + 8;
    u32* ganyf2 = g_gz + 136;
    if (bid == 0 && tid < NGZ) g_gz[tid] = 0u;

    conv_item<128,128,26,26,13,13,4,4,2,1,4,true>
        (sm, (bid & 7) * 16, bid >> 3, g_s1, w2, b2, g_s2, g_m1, g_m2,
         nullptr, 71.f);
    gsync();

    for (int item = bid; item < 384; item += NBLK)
        conv_item<128,192,13,13,13,13,3,3,1,1,8,true>
            (sm, (item % 12) * 16, item / 12, g_s2, w3, b3, g_s3, g_m2, g_m3,
             nullptr, 93.f);
    gsync();

    conv_item<192,128,13,13,13,13,3,3,1,1,8,true>
        (sm, (bid & 7) * 16, bid >> 3, g_s3, w4, b4, g_s4, g_m3, g_m4,
         nullptr, 144.f);
    gsync();

    conv_item<128,128,13,13,6,6,3,3,2,0,4,false>
        (sm, (bid & 7) * 16, bid >> 3, g_s4, w5, b5, g_s5, g_m4, nullptr,
         gany5, 79.f);
    gsync();

    gemm_stage(sm, g_s5, fc1w, g_zf1, 256, 2048, 4608, gany5, 36, 8);
    gsync();

    if_stage(g_zf1, g_sf1, 32*2048, 2048, gany5, 8, ganyf1, 2475.f);
    gsync();

    gemm_stage(sm, g_sf1, fc2w, g_zf2, 256, 512, 2048, ganyf1, 1, 128);
    gsync();

    if_stage(g_zf2, g_sf2, 32*512, 512, ganyf1, 128, ganyf2, 1357.f);
    gsync();

    fc3_stage(g_sf2, fc3w, out, ganyf2, 388.f);
}

// ---------------------------------------------------------------------------
extern "C" void kernel_launch(void* const* d_in, const int* in_sizes, int n_in,
                              void* d_out, int out_size)
{
    (void)in_sizes; (void)n_in; (void)out_size;
    const float* x    = (const float*)d_in[0];
    const float* w1   = (const float*)d_in[1];
    const float* b1   = (const float*)d_in[2];

    u8 *s1, *m1;
    cudaGetSymbolAddress((void**)&s1, g_s1);
    cudaGetSymbolAddress((void**)&m1, g_m1);

    conv1_if<<<NBLK, NTHR>>>(x, w1, b1, s1, m1, 13515.f);

    snn_tail<<<NBLK, NTHR>>>(
        (const float*)d_in[3],  (const float*)d_in[4],
        (const float*)d_in[5],  (const float*)d_in[6],
        (const float*)d_in[7],  (const float*)d_in[8],
        (const float*)d_in[9],  (const float*)d_in[10],
        (const float*)d_in[11], (const float*)d_in[12],
        (const float*)d_in[13], (float*)d_out);
}